// round 1
// baseline (speedup 1.0000x reference)
#include <cuda_runtime.h>
#include <math.h>

#define V      100000
#define E      1000000
#define D      200
#define R      474
#define HALF   500000
#define NPB    16        // nodes per block in main kernel
#define PAD    20        // xs row padding (floats) -> 16B-aligned float4 groups
#define TPB    224       // 7 warps, threads 0..199 own features
#define NBLK   98        // ceil(V/1024) for scan

// ---------------- device scratch (no runtime allocation allowed) ------------
__device__ float    g_Mtab[2 * R * D];   // softmax(rel @ W)/3, key = et + 474*is_out
__device__ float    g_Weff[D * D];       // (circ(loop_rel) @ loop_w)/3
__device__ int      g_cnt[V];
__device__ int      g_off[V + 1];
__device__ int      g_cur[V];
__device__ unsigned g_skey[E];
__device__ float    g_snorm[E];
__device__ int      g_bsum[128];
__device__ float    g_stats[4 * D];      // colsum, colsumsq, scale, shift

// ---------------- small precompute kernels ----------------------------------
__global__ void k_zero() {
    int i = blockIdx.x * blockDim.x + threadIdx.x;
    if (i < V) g_cnt[i] = 0;
    if (i < 2 * D) g_stats[i] = 0.f;
}

// Per-relation message table: softmax(rel_repr[r] @ W, axis=-1) * (1/3)
__global__ void k_mtab(const float* __restrict__ rel,
                       const float* __restrict__ in_w,
                       const float* __restrict__ out_w) {
    __shared__ float rr[D];
    __shared__ float red[256];
    int b = blockIdx.x;
    int s = b / R, r = b % R;
    const float* W = s ? out_w : in_w;
    int t = threadIdx.x;
    for (int i = t; i < D; i += 256) rr[i] = rel[r * D + i];
    __syncthreads();
    float dot = 0.f;
    if (t < D) {
        for (int j = 0; j < D; j++) dot += rr[j] * W[j * D + t];
    }
    red[t] = (t < D) ? dot : -INFINITY;
    __syncthreads();
    for (int ofs = 128; ofs > 0; ofs >>= 1) {
        if (t < ofs) red[t] = fmaxf(red[t], red[t + ofs]);
        __syncthreads();
    }
    float mx = red[0];
    __syncthreads();
    float e = (t < D) ? expf(dot - mx) : 0.f;
    red[t] = e;
    __syncthreads();
    for (int ofs = 128; ofs > 0; ofs >>= 1) {
        if (t < ofs) red[t] += red[t + ofs];
        __syncthreads();
    }
    float inv = (1.f / 3.f) / red[0];
    if (t < D) g_Mtab[(s * R + r) * D + t] = e * inv;
}

// W_eff[j,o] = sum_k loop_rel[(j+k)%D] * loop_w[k,o]  (then /3)
__global__ void k_weff(const float* __restrict__ loop_rel,
                       const float* __restrict__ loop_w) {
    __shared__ float lr[D];
    int j = blockIdx.x, t = threadIdx.x;
    for (int i = t; i < D; i += 256) lr[i] = loop_rel[i];
    __syncthreads();
    if (t < D) {
        float a = 0.f;
        int jj = j;
        for (int k = 0; k < D; k++) {
            a += lr[jj] * loop_w[k * D + t];
            jj++; if (jj == D) jj = 0;
        }
        g_Weff[j * D + t] = a * (1.f / 3.f);
    }
}

// rel_out = rel_repr @ w_rel  (second output, written straight to d_out tail)
__global__ void k_relout(const float* __restrict__ rel,
                         const float* __restrict__ w_rel,
                         float* __restrict__ out2) {
    __shared__ float rr[D];
    int r = blockIdx.x, t = threadIdx.x;
    for (int i = t; i < D; i += 256) rr[i] = rel[r * D + i];
    __syncthreads();
    if (t < D) {
        float a = 0.f;
        for (int j = 0; j < D; j++) a += rr[j] * w_rel[j * D + t];
        out2[r * D + t] = a;
    }
}

// ---------------- CSR build: histogram -> scan -> scatter -------------------
__global__ void k_hist(const int* __restrict__ dst) {
    int i = blockIdx.x * blockDim.x + threadIdx.x;
    if (i < E) atomicAdd(&g_cnt[dst[i]], 1);
}

__global__ void k_scan1() {
    __shared__ int sh[256];
    int b = blockIdx.x, t = threadIdx.x;
    int base = b * 1024 + t * 4;
    int s = 0;
    #pragma unroll
    for (int i = 0; i < 4; i++) {
        int v = base + i;
        if (v < V) s += g_cnt[v];
    }
    sh[t] = s;
    __syncthreads();
    for (int ofs = 128; ofs > 0; ofs >>= 1) {
        if (t < ofs) sh[t] += sh[t + ofs];
        __syncthreads();
    }
    if (t == 0) g_bsum[b] = sh[0];
}

__global__ void k_scan2() {
    if (threadIdx.x == 0) {
        int run = 0;
        for (int b = 0; b < NBLK; b++) {
            int c = g_bsum[b];
            g_bsum[b] = run;
            run += c;
        }
        g_off[V] = E;
    }
}

__global__ void k_scan3() {
    __shared__ int sh[256];
    int b = blockIdx.x, t = threadIdx.x;
    int base = b * 1024 + t * 4;
    int c[4];
    int local = 0;
    #pragma unroll
    for (int i = 0; i < 4; i++) {
        int v = base + i;
        c[i] = (v < V) ? g_cnt[v] : 0;
        local += c[i];
    }
    sh[t] = local;
    __syncthreads();
    for (int ofs = 1; ofs < 256; ofs <<= 1) {
        int val = 0;
        if (t >= ofs) val = sh[t - ofs];
        __syncthreads();
        sh[t] += val;
        __syncthreads();
    }
    int excl = sh[t] - local + g_bsum[b];
    #pragma unroll
    for (int i = 0; i < 4; i++) {
        int v = base + i;
        if (v < V) { g_off[v] = excl; g_cur[v] = excl; }
        excl += c[i];
    }
}

__global__ void k_scatter(const int* __restrict__ dst,
                          const int* __restrict__ et,
                          const float* __restrict__ norm) {
    int i = blockIdx.x * blockDim.x + threadIdx.x;
    if (i < E) {
        int v = dst[i];
        int p = atomicAdd(&g_cur[v], 1);
        g_skey[p]  = (unsigned)et[i] + ((i >= HALF) ? R : 0);
        g_snorm[p] = norm[i];
    }
}

// ---------------- fused main: gather-agg + x@Weff + stats -------------------
__global__ void __launch_bounds__(TPB) k_main(const float* __restrict__ x,
                                              const float* __restrict__ bias,
                                              float* __restrict__ out) {
    __shared__ float xs[D * PAD];   // transposed x tile: xs[j*PAD + n]
    int o  = threadIdx.x;
    int v0 = blockIdx.x * NPB;

    // coalesced load of 16 x-rows, transposed into shared
    for (int i = o; i < NPB * D; i += TPB) {
        int n = i / D, j = i % D;
        xs[j * PAD + n] = x[(v0 + n) * D + j];
    }
    __syncthreads();

    float acc[NPB];
    #pragma unroll
    for (int n = 0; n < NPB; n++) acc[n] = 0.f;

    if (o < D) {
        // edge aggregation (message table hot in L2)
        #pragma unroll 1
        for (int n = 0; n < NPB; n++) {
            int v = v0 + n;
            int s = g_off[v], t2 = g_off[v + 1];
            for (int e = s; e < t2; e++) {
                acc[n] += g_snorm[e] * g_Mtab[(int)g_skey[e] * D + o];
            }
        }

        // pack per-node-pair accumulators for f32x2 FMA
        unsigned long long acc2[NPB / 2];
        #pragma unroll
        for (int n = 0; n < NPB / 2; n++) {
            asm("mov.b64 %0, {%1, %2};"
                : "=l"(acc2[n]) : "f"(acc[2 * n]), "f"(acc[2 * n + 1]));
        }

        // loop-branch GEMM: acc += x @ Weff   (packed f32x2, 2x FMA rate)
        #pragma unroll 2
        for (int j = 0; j < D; j++) {
            float w = g_Weff[j * D + o];
            unsigned long long wd;
            asm("mov.b64 %0, {%1, %1};" : "=l"(wd) : "f"(w));
            const longlong2* xrow = (const longlong2*)&xs[j * PAD];
            #pragma unroll
            for (int m = 0; m < NPB / 4; m++) {
                longlong2 xq = xrow[m];   // LDS.128, broadcast across lanes
                asm("fma.rn.f32x2 %0, %1, %2, %0;"
                    : "+l"(acc2[2 * m]) : "l"((unsigned long long)xq.x), "l"(wd));
                asm("fma.rn.f32x2 %0, %1, %2, %0;"
                    : "+l"(acc2[2 * m + 1]) : "l"((unsigned long long)xq.y), "l"(wd));
            }
        }

        float b = bias[o];
        float lsum = 0.f, lsq = 0.f;
        #pragma unroll
        for (int n = 0; n < NPB / 2; n++) {
            float a0, a1;
            asm("mov.b64 {%0, %1}, %2;" : "=f"(a0), "=f"(a1) : "l"(acc2[n]));
            float p0 = a0 + b;
            float p1 = a1 + b;
            out[(v0 + 2 * n) * D + o]     = p0;
            out[(v0 + 2 * n + 1) * D + o] = p1;
            lsum += p0 + p1;
            lsq  += p0 * p0 + p1 * p1;
        }
        atomicAdd(&g_stats[o], lsum);
        atomicAdd(&g_stats[D + o], lsq);
    }
}

// ---------------- BN finalize + normalize -----------------------------------
__global__ void k_bn(const float* __restrict__ bnw, const float* __restrict__ bnb) {
    int o = threadIdx.x;
    if (o < D) {
        float mean = g_stats[o] * (1.f / (float)V);
        float var  = g_stats[D + o] * (1.f / (float)V) - mean * mean;
        float sc   = bnw[o] * rsqrtf(var + 1e-5f);
        g_stats[2 * D + o] = sc;
        g_stats[3 * D + o] = bnb[o] - mean * sc;
    }
}

__global__ void k_norm(float* __restrict__ out) {
    __shared__ float sc[D], sh[D];
    int t = threadIdx.x;
    for (int i = t; i < D; i += blockDim.x) {
        sc[i] = g_stats[2 * D + i];
        sh[i] = g_stats[3 * D + i];
    }
    __syncthreads();
    const int n4 = V * D / 4;
    for (int i = blockIdx.x * blockDim.x + t; i < n4; i += gridDim.x * blockDim.x) {
        float4 v = ((float4*)out)[i];
        int o = (i * 4) % D;
        v.x = v.x * sc[o]     + sh[o];
        v.y = v.y * sc[o + 1] + sh[o + 1];
        v.z = v.z * sc[o + 2] + sh[o + 2];
        v.w = v.w * sc[o + 3] + sh[o + 3];
        ((float4*)out)[i] = v;
    }
}

// ---------------- launch ----------------------------------------------------
extern "C" void kernel_launch(void* const* d_in, const int* in_sizes, int n_in,
                              void* d_out, int out_size) {
    const float* x        = (const float*)d_in[0];
    const float* rel      = (const float*)d_in[1];
    const float* enorm    = (const float*)d_in[2];
    const float* in_w     = (const float*)d_in[3];
    const float* out_w    = (const float*)d_in[4];
    const float* loop_w   = (const float*)d_in[5];
    const float* w_rel    = (const float*)d_in[6];
    const float* loop_rel = (const float*)d_in[7];
    const float* bias     = (const float*)d_in[8];
    const float* bnw      = (const float*)d_in[9];
    const float* bnb      = (const float*)d_in[10];
    const int*   et       = (const int*)d_in[11];
    const int*   dst      = (const int*)d_in[12];
    float*       out      = (float*)d_out;

    k_zero<<<(V + 255) / 256, 256>>>();
    k_mtab<<<2 * R, 256>>>(rel, in_w, out_w);
    k_weff<<<D, 256>>>(loop_rel, loop_w);
    k_relout<<<R, 256>>>(rel, w_rel, out + (size_t)V * D);
    k_hist<<<(E + 255) / 256, 256>>>(dst);
    k_scan1<<<NBLK, 256>>>();
    k_scan2<<<1, 32>>>();
    k_scan3<<<NBLK, 256>>>();
    k_scatter<<<(E + 255) / 256, 256>>>(dst, et, enorm);
    k_main<<<V / NPB, TPB>>>(x, bias, out);
    k_bn<<<1, 256>>>(bnw, bnb);
    k_norm<<<1024, 256>>>(out);
}